// round 11
// baseline (speedup 1.0000x reference)
#include <cuda_runtime.h>
#include <cuda_bf16.h>

#define BB 8
#define LL 4096
#define DD 1024
#define CC 128
#define SLICE 32
#define MAXSL (LL / SLICE + CC)   // 256 slice slots per batch
#define PPB (MAXSL / 2)           // 128 pool blocks per batch (2 slices each)

// Packed metadata
__device__ int4 g_slice[BB][MAXSL];   // {s, e, chunk_id, 0}; s==e => unused
__device__ int4 g_chunk[BB][CC];      // {cnt, first slice, n slices, 0}
__device__ int  g_arrive[BB][CC];     // per-chunk arrival counters (reset by scan)
__device__ int  g_ready[BB];          // per-batch metadata-ready flags (self-cleaning)
__device__ int  g_done[BB];           // per-batch pool-block completion counters

// Partial sums scratch (multi-slice chunks only): 8 MB
__device__ float4 g_part[BB][MAXSL][DD / 4];

// --- memory-model helpers ---
__device__ __forceinline__ int atomic_add_acq_rel(int* p, int v) {
    int old;
    asm volatile("atom.add.acq_rel.gpu.s32 %0, [%1], %2;"
                 : "=r"(old) : "l"(p), "r"(v) : "memory");
    return old;
}
__device__ __forceinline__ void st_release(int* p, int v) {
    asm volatile("st.release.gpu.s32 [%0], %1;" :: "l"(p), "r"(v) : "memory");
}
__device__ __forceinline__ int ld_acquire(const int* p) {
    int v;
    asm volatile("ld.acquire.gpu.s32 %0, [%1];" : "=r"(v) : "l"(p) : "memory");
    return v;
}
__device__ __forceinline__ void prefetch_l2(const void* p) {
    asm volatile("prefetch.global.L2 [%0];" :: "l"(p));
}

// Cold path: deterministic fixed-order reduction of a chunk's slice partials.
__device__ __noinline__ void finalize_multi(int b, int c, int t,
                                            int first_sl, int nsl, int cnt,
                                            float4* __restrict__ mp) {
    float4 acc = make_float4(0.f, 0.f, 0.f, 0.f);
    for (int i = 0; i < nsl; i++) {
        float4 v = g_part[b][first_sl + i][t];
        acc.x += v.x; acc.y += v.y; acc.z += v.z; acc.w += v.w;
    }
    const float inv = 1.0f / (float)cnt;
    acc.x *= inv; acc.y *= inv; acc.z *= inv; acc.w *= inv;
    mp[t] = acc;
}

// ---------------------------------------------------------------------------
// One fused kernel, 8 + 1024 blocks (single wave at 8 CTAs/SM), 256 threads.
//   bid 0..7    : per-batch boundary scan -> metadata; release ready flag.
//   bid 8..1031 : pool blocks; prefetch static x region, spin, then process
//                 slice slots {2j, 2j+1}.
// ---------------------------------------------------------------------------
__global__ void __launch_bounds__(256, 8) chunk_fused_kernel(
        const float* __restrict__ x,
        const float* __restrict__ boundaries,
        float* __restrict__ means,
        float* __restrict__ cnts_out,
        int write_cnts) {
    const int t    = threadIdx.x;       // 0..255
    const int lane = t & 31;
    const int wid  = t >> 5;            // 0..7

    if (blockIdx.x < BB) {
        // =================== SCAN BLOCK (one per batch) ====================
        const int b = blockIdx.x;
        const float* bp = boundaries + (size_t)b * LL;

        __shared__ int wsum[8], wexcl[8], pos[CC + 1], snb, csum[4], cexcl[4];
        __shared__ int snsl, elist[CC], s_ne;
        if (t == 0) s_ne = 0;

        // phase 1: flags (16 tokens/thread) + ordered compaction
        const int base = t * 16;
        unsigned flags = 0;
        {
            const float4* bp4 = reinterpret_cast<const float4*>(bp + base);
#pragma unroll
            for (int q = 0; q < 4; q++) {
                float4 v = bp4[q];
                if (v.x > 0.5f) flags |= 1u << (q * 4 + 0);
                if (v.y > 0.5f) flags |= 1u << (q * 4 + 1);
                if (v.z > 0.5f) flags |= 1u << (q * 4 + 2);
                if (v.w > 0.5f) flags |= 1u << (q * 4 + 3);
            }
        }
        const int cnt = __popc(flags);

        int incl = cnt;
#pragma unroll
        for (int d = 1; d < 32; d <<= 1) {
            int v = __shfl_up_sync(0xFFFFFFFFu, incl, d);
            if (lane >= d) incl += v;
        }
        if (lane == 31) wsum[wid] = incl;
        __syncthreads();

        if (t < 8) {
            int v = wsum[t];
            int iv = v;
#pragma unroll
            for (int d = 1; d < 8; d <<= 1) {
                int u = __shfl_up_sync(0x000000FFu, iv, d);
                if (t >= d) iv += u;
            }
            wexcl[t] = iv - v;
            if (t == 7) snb = iv;
        }
        __syncthreads();

        {
            int idx = wexcl[wid] + (incl - cnt);
            unsigned f = flags;
            while (f) {
                int i = __ffs(f) - 1;
                f &= f - 1;
                if (idx <= CC) pos[idx] = base + i;
                idx++;
            }
        }
        __syncthreads();

        const int nb = snb;
        const int valid = nb < CC ? nb : CC;

        // phase 2: chunk ranges + slice-count scan
        int s0 = 0, e0 = 0, len = 0, nsl = 0;
        if (t < CC && t < valid) {
            s0 = pos[t];
            e0 = (t + 1 < nb) ? pos[t + 1] : LL;
            len = e0 - s0;
            nsl = (len + SLICE - 1) / SLICE;
        }

        int cincl = nsl;
#pragma unroll
        for (int d = 1; d < 32; d <<= 1) {
            int v = __shfl_up_sync(0xFFFFFFFFu, cincl, d);
            if (lane >= d) cincl += v;
        }
        if (t < CC && lane == 31) csum[wid] = cincl;
        __syncthreads();

        if (t < 4) {
            int v = csum[t];
            int iv = v;
#pragma unroll
            for (int d = 1; d < 4; d <<= 1) {
                int u = __shfl_up_sync(0x0000000Fu, iv, d);
                if (t >= d) iv += u;
            }
            cexcl[t] = iv - v;
            if (t == 3) snsl = iv;
        }
        __syncthreads();

        const int nsl_total = snsl;

        if (t < CC) {
            const int soff = cexcl[wid] + (cincl - nsl);
            g_chunk[b][t]  = make_int4(len, soff, nsl, 0);
            g_arrive[b][t] = 0;
            if (len > 0) {
                int si = soff;
                for (int ss = s0; ss < e0; ss += SLICE, si++) {
                    int ee = ss + SLICE;
                    g_slice[b][si] = make_int4(ss, ee < e0 ? ee : e0, t, 0);
                }
            } else {
                elist[atomicAdd(&s_ne, 1)] = t;
            }
        }
        if (t >= nsl_total) g_slice[b][t] = make_int4(0, 0, 0, 0);
        __syncthreads();

        if (t == 0) st_release(&g_ready[b], 1);   // publish EARLY

        // post-release: zero empty-chunk means + cnts output
        const int ne = s_ne;
        {
            const float4 z = make_float4(0.f, 0.f, 0.f, 0.f);
            for (int i = 0; i < ne; i++) {
                reinterpret_cast<float4*>(
                    means + ((size_t)b * CC + elist[i]) * DD)[t] = z;
            }
        }
        if (write_cnts && t < CC) cnts_out[b * CC + t] = (float)g_chunk[b][t].x;
        return;
    }

    // ======================= POOL BLOCK =======================
    const int idx = blockIdx.x - BB;     // 0..1023
    const int b   = idx >> 7;            // / PPB
    const int j   = idx & (PPB - 1);     // pair index 0..127

    __shared__ int s_last;

    // prefetch a static 32KB region of x (8 tokens) while the scan runs:
    // address independent of scan output -> DRAM busy from cycle ~0.
    {
        const char* pre = reinterpret_cast<const char*>(x) +
                          ((size_t)b * LL + (size_t)j * 32) * (DD * 4);
        prefetch_l2(pre + t * 128);           // 256 threads * 128B = 32KB
    }

    if (t == 0) {
        while (ld_acquire(&g_ready[b]) == 0) __nanosleep(32);
    }
    __syncthreads();                      // distribute acquire to all threads

#pragma unroll
    for (int k = 0; k < 2; k++) {
        const int sl = 2 * j + k;

        const int4 se = g_slice[b][sl];   // {s, e, chunk, 0}
        const int n = se.y - se.x;
        if (n == 0) continue;

        // 32-bit offset math (fits: 8*4096*1024 < 2^31)
        const float4* __restrict__ xp =
            reinterpret_cast<const float4*>(x) +
            (b * LL + se.x) * (DD / 4) + t;

        float4 a0 = make_float4(0.f, 0.f, 0.f, 0.f);
        float4 a1 = make_float4(0.f, 0.f, 0.f, 0.f);

        if (n == SLICE) {
#pragma unroll
            for (int i = 0; i < SLICE; i += 2) {
                float4 v0 = xp[(i + 0) * (DD / 4)];
                float4 v1 = xp[(i + 1) * (DD / 4)];
                a0.x += v0.x; a0.y += v0.y; a0.z += v0.z; a0.w += v0.w;
                a1.x += v1.x; a1.y += v1.y; a1.z += v1.z; a1.w += v1.w;
            }
        } else {
            int i = 0;
#pragma unroll 4
            for (; i + 1 < n; i += 2) {
                float4 v0 = xp[(i + 0) * (DD / 4)];
                float4 v1 = xp[(i + 1) * (DD / 4)];
                a0.x += v0.x; a0.y += v0.y; a0.z += v0.z; a0.w += v0.w;
                a1.x += v1.x; a1.y += v1.y; a1.z += v1.z; a1.w += v1.w;
            }
            if (i < n) {
                float4 v0 = xp[i * (DD / 4)];
                a0.x += v0.x; a0.y += v0.y; a0.z += v0.z; a0.w += v0.w;
            }
        }
        a0.x += a1.x; a0.y += a1.y; a0.z += a1.z; a0.w += a1.w;

        const int c = se.z;
        const int4 meta = g_chunk[b][c];  // {cnt, first slice, nsl, 0}
        float4* __restrict__ mp =
            reinterpret_cast<float4*>(means + ((size_t)b * CC + c) * DD);

        if (meta.z == 1) {
            const float inv = 1.0f / (float)n;
            a0.x *= inv; a0.y *= inv; a0.z *= inv; a0.w *= inv;
            mp[t] = a0;
        } else {
            g_part[b][sl][t] = a0;
            __syncthreads();              // all partial stores before t0's release
            if (t == 0) {
                s_last = (atomic_add_acq_rel(&g_arrive[b][c], 1) == meta.z - 1);
            }
            __syncthreads();              // distribute acquire
            if (s_last) {
                finalize_multi(b, c, t, meta.y, meta.z, meta.x, mp);
            }
        }
    }

    // self-cleaning for graph replay: last pool block of the batch resets flags
    if (t == 0) {
        int old = atomic_add_acq_rel(&g_done[b], 1);
        if (old == PPB - 1) {
            g_ready[b] = 0;
            g_done[b]  = 0;
        }
    }
}

extern "C" void kernel_launch(void* const* d_in, const int* in_sizes, int n_in,
                              void* d_out, int out_size) {
    const float* x = nullptr;
    const float* boundaries = nullptr;
    for (int i = 0; i < n_in; i++) {
        if (in_sizes[i] == BB * LL * DD) x = (const float*)d_in[i];
        else if (in_sizes[i] == BB * LL) boundaries = (const float*)d_in[i];
    }

    float* out = (float*)d_out;
    const int means_elems = BB * CC * DD;
    const int write_cnts = (out_size > means_elems) ? 1 : 0;

    chunk_fused_kernel<<<BB + BB * PPB, 256>>>(
        x, boundaries, out, out + means_elems, write_cnts);
}